// round 1
// baseline (speedup 1.0000x reference)
#include <cuda_runtime.h>
#include <cuda_bf16.h>
#include <math.h>

// Problem constants
#define B_    4
#define T_    2048
#define DM    1024
#define NH    16
#define DH    64
#define ROWS  (B_ * T_)          // 8192
#define QKV_N (3 * DM)           // 3072

// Scratch (device globals: allocation-free)
__device__ float g_qkv[ROWS * QKV_N];    // [8192, 3072]
__device__ float g_attn[ROWS * DM];      // [8192, 1024]

// ---------------------------------------------------------------------------
// SGEMM: C[M,N] = A[M,K] @ B[K,N], row-major, all dims multiples of tile sizes
// 128x128 block tile, BK=8, 256 threads, 8x8 per thread.
// ---------------------------------------------------------------------------
__global__ __launch_bounds__(256) void sgemm_kernel(
    const float* __restrict__ A, const float* __restrict__ B,
    float* __restrict__ C, int M, int N, int K)
{
    __shared__ float As[8][128];
    __shared__ float Bs[8][128];

    const int tid = threadIdx.x;
    const int bm = blockIdx.y * 128;
    const int bn = blockIdx.x * 128;

    const int tx = tid & 15;          // 0..15
    const int ty = tid >> 4;          // 0..15
    const int row0 = ty * 8;
    const int col0 = tx * 8;

    // loader mapping
    const int arow  = tid >> 1;            // 0..127
    const int acol4 = (tid & 1) * 4;       // 0 or 4
    const int brow  = tid >> 5;            // 0..7
    const int bcol4 = (tid & 31) * 4;      // 0..124

    const float* Aptr = A + (size_t)(bm + arow) * K + acol4;
    const float* Bptr = B + (size_t)brow * N + bn + bcol4;

    float acc[8][8];
#pragma unroll
    for (int i = 0; i < 8; ++i)
#pragma unroll
        for (int j = 0; j < 8; ++j) acc[i][j] = 0.f;

    for (int k0 = 0; k0 < K; k0 += 8) {
        float4 av = *(const float4*)(Aptr + k0);
        float4 bv = *(const float4*)(Bptr + (size_t)k0 * N);
        As[acol4 + 0][arow] = av.x;
        As[acol4 + 1][arow] = av.y;
        As[acol4 + 2][arow] = av.z;
        As[acol4 + 3][arow] = av.w;
        *(float4*)&Bs[brow][bcol4] = bv;
        __syncthreads();

#pragma unroll
        for (int k = 0; k < 8; ++k) {
            float a[8], b[8];
            *(float4*)&a[0] = *(const float4*)&As[k][row0];
            *(float4*)&a[4] = *(const float4*)&As[k][row0 + 4];
            *(float4*)&b[0] = *(const float4*)&Bs[k][col0];
            *(float4*)&b[4] = *(const float4*)&Bs[k][col0 + 4];
#pragma unroll
            for (int i = 0; i < 8; ++i)
#pragma unroll
                for (int j = 0; j < 8; ++j)
                    acc[i][j] += a[i] * b[j];
        }
        __syncthreads();
    }

#pragma unroll
    for (int i = 0; i < 8; ++i) {
        float* crow = C + (size_t)(bm + row0 + i) * N + bn + col0;
        float4 c0, c1;
        c0.x = acc[i][0]; c0.y = acc[i][1]; c0.z = acc[i][2]; c0.w = acc[i][3];
        c1.x = acc[i][4]; c1.y = acc[i][5]; c1.z = acc[i][6]; c1.w = acc[i][7];
        *(float4*)(crow)     = c0;
        *(float4*)(crow + 4) = c1;
    }
}

// ---------------------------------------------------------------------------
// Flash attention (no mask), fp32.
// Grid: (T/64, B*NH). Block: 256 threads.
// Thread (r = tid/4, quarter = tid%4): owns S/P/O columns [quarter*16, +16)
// of row r within the 64-row Q tile. Q row kept in registers.
// smem: Ks[64][68], Vs[64][68], Ps[64][68] (Ps also stages Q).
// ---------------------------------------------------------------------------
#define FSTR 68
#define FSM  (64 * FSTR)

__global__ __launch_bounds__(256) void flash_kernel(
    const float* __restrict__ qkv, float* __restrict__ attn)
{
    extern __shared__ float sm[];
    float* Ks = sm;
    float* Vs = sm + FSM;
    float* Ps = sm + 2 * FSM;   // also Q staging

    const int tid = threadIdx.x;
    const int qt  = blockIdx.x;          // q tile 0..31
    const int bh  = blockIdx.y;          // 0..63
    const int b   = bh >> 4;
    const int h   = bh & 15;

    const int r       = tid >> 2;        // 0..63
    const int quarter = tid & 3;

    // ---- stage Q tile into Ps, then into registers (scaled) ----
#pragma unroll
    for (int i = 0; i < 4; ++i) {
        int idx = tid + i * 256;         // 0..1023 (float4 index)
        int row = idx >> 4;
        int c4  = idx & 15;
        const float4 v = *(const float4*)&qkv[
            (size_t)(b * T_ + qt * 64 + row) * QKV_N + h * DH + c4 * 4];
        *(float4*)&Ps[row * FSTR + c4 * 4] = v;
    }
    __syncthreads();

    float q[64];
#pragma unroll
    for (int d = 0; d < 64; ++d) q[d] = Ps[r * FSTR + d] * 0.125f; // 1/sqrt(64)
    __syncthreads();   // everyone has Q before Ps is reused

    float O[16];
#pragma unroll
    for (int i = 0; i < 16; ++i) O[i] = 0.f;
    float m = -INFINITY;
    float l = 0.f;

    for (int j = 0; j < T_ / 64; ++j) {
        // ---- load K, V tiles ----
#pragma unroll
        for (int i = 0; i < 4; ++i) {
            int idx = tid + i * 256;
            int row = idx >> 4;
            int c4  = idx & 15;
            size_t g = (size_t)(b * T_ + j * 64 + row) * QKV_N + h * DH + c4 * 4;
            float4 kv = *(const float4*)&qkv[g + DM];
            float4 vv = *(const float4*)&qkv[g + 2 * DM];
            *(float4*)&Ks[row * FSTR + c4 * 4] = kv;
            *(float4*)&Vs[row * FSTR + c4 * 4] = vv;
        }
        __syncthreads();

        // ---- S = q . K^T for 16 columns ----
        float s[16];
#pragma unroll
        for (int c = 0; c < 16; ++c) {
            const float4* krow =
                (const float4*)&Ks[(quarter * 16 + c) * FSTR];
            float a0 = 0.f, a1 = 0.f;
#pragma unroll
            for (int d4 = 0; d4 < 16; d4 += 2) {
                float4 k0 = krow[d4];
                float4 k1 = krow[d4 + 1];
                a0 += q[4*d4+0]*k0.x + q[4*d4+1]*k0.y + q[4*d4+2]*k0.z + q[4*d4+3]*k0.w;
                a1 += q[4*d4+4]*k1.x + q[4*d4+5]*k1.y + q[4*d4+6]*k1.z + q[4*d4+7]*k1.w;
            }
            s[c] = a0 + a1;
        }

        // ---- online softmax (4-lane row groups) ----
        float mloc = s[0];
#pragma unroll
        for (int c = 1; c < 16; ++c) mloc = fmaxf(mloc, s[c]);
        mloc = fmaxf(mloc, __shfl_xor_sync(0xffffffffu, mloc, 1));
        mloc = fmaxf(mloc, __shfl_xor_sync(0xffffffffu, mloc, 2));

        float mnew = fmaxf(m, mloc);
        float corr = __expf(m - mnew);

        float lloc = 0.f;
#pragma unroll
        for (int c = 0; c < 16; ++c) {
            float p = __expf(s[c] - mnew);
            Ps[r * FSTR + quarter * 16 + c] = p;
            lloc += p;
        }
        lloc += __shfl_xor_sync(0xffffffffu, lloc, 1);
        lloc += __shfl_xor_sync(0xffffffffu, lloc, 2);

        l = l * corr + lloc;
        m = mnew;
#pragma unroll
        for (int i = 0; i < 16; ++i) O[i] *= corr;
        __syncwarp();

        // ---- O += P @ V ----
#pragma unroll 4
        for (int k = 0; k < 64; ++k) {
            float p = Ps[r * FSTR + k];
            const float4* vrow = (const float4*)&Vs[k * FSTR + quarter * 16];
#pragma unroll
            for (int c4 = 0; c4 < 4; ++c4) {
                float4 vv = vrow[c4];
                O[c4 * 4 + 0] += p * vv.x;
                O[c4 * 4 + 1] += p * vv.y;
                O[c4 * 4 + 2] += p * vv.z;
                O[c4 * 4 + 3] += p * vv.w;
            }
        }
        __syncthreads();   // before Ks/Vs are overwritten
    }

    const float inv = 1.f / l;
    float* orow = attn + (size_t)(b * T_ + qt * 64 + r) * DM + h * DH + quarter * 16;
#pragma unroll
    for (int c4 = 0; c4 < 4; ++c4) {
        float4 o;
        o.x = O[c4 * 4 + 0] * inv;
        o.y = O[c4 * 4 + 1] * inv;
        o.z = O[c4 * 4 + 2] * inv;
        o.w = O[c4 * 4 + 3] * inv;
        *(float4*)(orow + c4 * 4) = o;
    }
}

// ---------------------------------------------------------------------------
extern "C" void kernel_launch(void* const* d_in, const int* in_sizes, int n_in,
                              void* d_out, int out_size)
{
    const float* x      = (const float*)d_in[0];   // [4,2048,1024]
    const float* w_qkv  = (const float*)d_in[1];   // [1024,3072]
    const float* w_proj = (const float*)d_in[2];   // [1024,1024]
    float* out = (float*)d_out;                    // [4,2048,1024]

    float* qkvbuf = nullptr;
    float* attnbuf = nullptr;
    cudaGetSymbolAddress((void**)&qkvbuf, g_qkv);
    cudaGetSymbolAddress((void**)&attnbuf, g_attn);

    static bool attr_set = false;
    if (!attr_set) {
        cudaFuncSetAttribute(flash_kernel,
                             cudaFuncAttributeMaxDynamicSharedMemorySize,
                             3 * FSM * (int)sizeof(float));
        attr_set = true;
    }

    // 1) QKV projection: [8192,1024] @ [1024,3072]
    {
        dim3 grid(QKV_N / 128, ROWS / 128);
        sgemm_kernel<<<grid, 256>>>(x, w_qkv, qkvbuf, ROWS, QKV_N, DM);
    }

    // 2) Attention
    {
        dim3 grid(T_ / 64, B_ * NH);
        flash_kernel<<<grid, 256, 3 * FSM * (int)sizeof(float)>>>(qkvbuf, attnbuf);
    }

    // 3) Output projection: [8192,1024] @ [1024,1024]
    {
        dim3 grid(DM / 128, ROWS / 128);
        sgemm_kernel<<<grid, 256>>>(attnbuf, w_proj, out, ROWS, DM, DM);
    }
}